// round 11
// baseline (speedup 1.0000x reference)
#include <cuda_runtime.h>
#include <cuda_bf16.h>
#include <cstdint>

#define N_CELLS 600
#define HW      4096
#define NBF     100
#define MC      20
#define EDGES   21
#define NB      500
#define NB_INIT 100
#define BATCH   32
#define NSTEPS  400
#define ROW     (N_CELLS*BATCH)   /* 19200 */

// 5 cells per CTA, 4 warps per cell; 28 slots/warp; ring stride 116 (112 slots + 4 zero pad)
#define CPC     5
#define WPC     4
#define SLOTS   28
#define NPW     14
#define RING2   116
#define TPB     (CPC*WPC*32)       /* 640 */
#define NCTA    (N_CELLS/CPC)      /* 120 CTAs = 1/SM uniform */
#define NBODY   (NB/2)             /* 250 fused 2-step bodies */

// dynamic smem layout (bytes, all 16-aligned)
#define OFF_W    0                 /* float[CPC][EDGES][RING2] = 48720 */
#define OFF_STV  48720             /* float[CPC][NSTEPS] = 8000 */
#define OFF_SRC  56720             /* int[CPC][EDGES] pad448 */
#define OFF_WH   57168             /* float[CPC][EDGES] w_rev[0]=filter[99], pad448 */
#define OFF_WH2  57616             /* float[CPC][EDGES] w_rev[1]=filter[98], pad448 */
#define OFF_SPKA 58064             /* float[2][CPC][32] even-row self spike */
#define OFF_SPKB 59344             /* float[2][CPC][32] odd-row self spike */
#define OFF_BND  60624             /* u64 [2][CPC][WPC][32] boundary pair */
#define SMEM_DYN 70880

// ---------------- scratch (no allocations allowed). +1 pad row for tail prefetch ----
__device__ float g_spk [(NB+1) * N_CELLS * BATCH];  // [t][c][b], canary -1 until written
__device__ float g_gens[NSTEPS * N_CELLS * BATCH];  // [t'][c][b]
__device__ float g_stimT[HW * BATCH];               // [hw][b]
__device__ float g_sapp [N_CELLS * BATCH];          // [c][b]

// ---------------- helpers ----------------
__device__ __forceinline__ float ldg_relaxed(const float* p) {
    float v;
    asm volatile("ld.relaxed.gpu.global.f32 %0, [%1];" : "=f"(v) : "l"(p));
    return v;
}
__device__ __forceinline__ void stg_relaxed(float* p, float v) {
    asm volatile("st.relaxed.gpu.global.f32 [%0], %1;" :: "l"(p), "f"(v) : "memory");
}
__device__ __forceinline__ unsigned long long pk2(float lo, float hi) {
    unsigned long long u;
    asm("mov.b64 %0, {%1, %2};" : "=l"(u) : "f"(lo), "f"(hi));
    return u;
}
__device__ __forceinline__ float lo2(unsigned long long u) {
    float a, b;
    asm("mov.b64 {%0, %1}, %2;" : "=f"(a), "=f"(b) : "l"(u));
    return a;
}
__device__ __forceinline__ float hi2(unsigned long long u) {
    float a, b;
    asm("mov.b64 {%0, %1}, %2;" : "=f"(a), "=f"(b) : "l"(u));
    return b;
}
__device__ __forceinline__ void fma2(unsigned long long& acc, unsigned long long w, unsigned long long s) {
    asm("fma.rn.f32x2 %0, %1, %2, %0;" : "+l"(acc) : "l"(w), "l"(s));
}
__device__ __forceinline__ void cellbar(int id) {
    asm volatile("bar.sync %0, %1;" :: "r"(id), "r"(WPC*32) : "memory");
}

// ---------------- setup kernels ----------------
__global__ void k_stimT(const float* __restrict__ stim) {
    int b = blockIdx.x;
    for (int i = threadIdx.x; i < HW; i += blockDim.x)
        g_stimT[i*BATCH + b] = stim[(size_t)b*HW + i];
}

__global__ void k_sapp(const float* __restrict__ spat) {
    __shared__ float red[128];
    int c = blockIdx.x, tid = threadIdx.x;
    int g = tid >> 5, b = tid & 31;
    float acc = 0.f;
    const float* sp = spat + (size_t)c*HW;
    #pragma unroll 8
    for (int m = 0; m < HW/4; m++) {
        int i = g + 4*m;
        acc += sp[i] * g_stimT[i*BATCH + b];
    }
    red[tid] = acc;
    __syncthreads();
    if (tid < 32)
        g_sapp[c*BATCH + tid] = red[tid] + red[tid+32] + red[tid+64] + red[tid+96];
}

__global__ void k_init(const float* __restrict__ init) {
    int idx = blockIdx.x*blockDim.x + threadIdx.x;
    if (idx >= NB*ROW) return;
    int tau = idx / ROW, r = idx % ROW;
    int cc = r / BATCH, b = r % BATCH;
    g_spk[idx] = (tau < NB_INIT) ? init[((size_t)b*N_CELLS + cc)*NB_INIT + tau] : -1.0f;
}

// ---------------- simulation: 2-step fused systolic ring, 250 bodies -----------------
__global__ void __launch_bounds__(TPB, 1)
k_sim(const float* __restrict__ stime, const float* __restrict__ tcf,
      const float* __restrict__ fbf,  const float* __restrict__ cpf,
      const float* __restrict__ bias, const int* __restrict__ sel)
{
    extern __shared__ __align__(16) char dyn[];
    float* sw   = (float*)(dyn + OFF_W);     // ring weights; j<2 and j>=100 ZERO
    float* sstv = (float*)(dyn + OFF_STV);
    int*   ssrc = (int*)  (dyn + OFF_SRC);
    float* swh  = (float*)(dyn + OFF_WH);    // w_rev[0] = filter[99]
    float* swh2 = (float*)(dyn + OFF_WH2);   // w_rev[1] = filter[98]
    float* spkA = (float*)(dyn + OFF_SPKA);  // [par][lc][32] even-row (tau) self spike
    float* spkB = (float*)(dyn + OFF_SPKB);  // [par][lc][32] odd-row (tau+1) self spike
    unsigned long long* sbnd = (unsigned long long*)(dyn + OFF_BND);

    const int tid = threadIdx.x;
    const int c0 = blockIdx.x * CPC;

    // ---- prologue: weights (tap-reversed, j==0,1 extracted, zero-padded) ----
    for (int i = tid; i < CPC*EDGES*RING2; i += TPB) {
        int lc = i/(EDGES*RING2), rr = i%(EDGES*RING2);
        int e = rr/RING2, j = rr%RING2;
        int c = c0 + lc;
        float v = 0.0f;
        if (j >= 2 && j < NBF)
            v = (e == 0) ? fbf[(size_t)c*NBF + (NBF-1-j)]
                         : cpf[((size_t)c*MC + (e-1))*NBF + (NBF-1-j)];
        sw[i] = v;
    }
    for (int i = tid; i < CPC*EDGES; i += TPB) {
        int lc = i/EDGES, e = i%EDGES;
        int c = c0 + lc;
        ssrc[i] = ((e == 0) ? c : sel[c*MC + (e-1)]) * BATCH;
        swh[i]  = (e == 0) ? fbf[(size_t)c*NBF + (NBF-1)]
                           : cpf[((size_t)c*MC + (e-1))*NBF + (NBF-1)];
        swh2[i] = (e == 0) ? fbf[(size_t)c*NBF + (NBF-2)]
                           : cpf[((size_t)c*MC + (e-1))*NBF + (NBF-2)];
    }
    for (int i = tid; i < CPC*NSTEPS; i += TPB) {
        int lc = i/NSTEPS, t = i%NSTEPS;
        int c = c0 + lc;
        float s = 0.f;
        #pragma unroll 4
        for (int f = 0; f < NBF; f++)
            s += __ldg(stime + t + f) * __ldg(tcf + (size_t)c*NBF + f);
        sstv[i] = s;
    }
    __syncthreads();

    const int wid = tid >> 5, lane = tid & 31;
    const int lc = wid % CPC, r = wid / CPC;    // SMSP-balanced: publishers spread
    const int c = c0 + lc;
    const int barid = lc + 1;
    const int myoff = c*BATCH + lane;
    const float sapp = g_sapp[myoff];
    const float bv = bias[c];
    const float* stvp = sstv + lc*NSTEPS;
    const float* whp  = swh  + lc*EDGES;
    const float* wh2p = swh2 + lc*EDGES;
    const int*   srcp = ssrc + lc*EDGES;
    const float* wseg = sw + lc*(EDGES*RING2) + r*SLOTS;

    float s_a = 0.0f;                           // r0: own spike at even row tau
    if (r == 0) {
        s_a = g_spk[myoff];
        spkA[(0*CPC + lc)*32 + lane] = s_a;     // body 0 (par=0)
    }

    unsigned long long accp[NPW];
    #pragma unroll
    for (int p = 0; p < NPW; p++) accp[p] = 0ull;
    __syncthreads();

    // prologue prefetch: row 0 (init-written)
    float sva[EDGES-1], svb[EDGES-1];
    #pragma unroll
    for (int e = 1; e < EDGES; e++) sva[e-1] = ldg_relaxed(g_spk + srcp[e] + lane);

    #pragma unroll 1
    for (int body = 0; body < NBODY; body++) {
        const int tau = body*2;
        const int par = body & 1;
        const float* rowa = g_spk + (size_t)tau*ROW;
        const float* rowb = rowa + ROW;

        // ---- validate sva (row tau, prefetched last body) ----
        if (tau >= NB_INIT) {
            float mn = sva[0];
            #pragma unroll
            for (int e = 1; e < EDGES-1; e++) mn = fminf(mn, sva[e]);
            if (__any_sync(0xffffffffu, mn < -0.5f)) {
                #pragma unroll
                for (int e = 0; e < EDGES-1; e++) {
                    int guard = 0;
                    while (__any_sync(0xffffffffu, sva[e] == -1.0f)) {
                        sva[e] = ldg_relaxed(rowa + srcp[e+1] + lane);
                        if (++guard > (1 << 22)) break;
                    }
                }
            }
        }

        // ---- r0: publish s(tau+1) EARLY (pre-shift slot1 + tap f=99), stash it.
        //      r>0: export pre-shift accp[0] pair (both slots travel together). ----
        float s_b = 0.0f;
        if (r == 0) {
            const int tn = tau + 1;
            if (tn >= NB_INIT) {
                float h = hi2(accp[0]);
                h = fmaf(whp[0], s_a, h);
                #pragma unroll
                for (int e = 1; e < EDGES; e++) h = fmaf(whp[e], sva[e-1], h);
                float gv = h + sapp * stvp[tn - NB_INIT] + bv;
                s_b = __fdividef(1.0f, 1.0f + __expf(-gv));
                g_gens[(size_t)(tn - NB_INIT)*ROW + myoff] = gv;
                stg_relaxed(&g_spk[(size_t)tn*ROW + myoff], s_b);
            } else {
                s_b = g_spk[(size_t)tn*ROW + myoff];
            }
            spkB[(par*CPC + lc)*32 + lane] = s_b;
        } else {
            sbnd[((par*CPC + lc)*WPC + r)*32 + lane] = accp[0];
        }
        cellbar(barid);

        // ---- import boundary pair; shift ring by TWO slots (pair-wise move) ----
        unsigned long long inc = 0ull;
        if (r < WPC-1) inc = sbnd[((par*CPC + lc)*WPC + (r+1))*32 + lane];
        #pragma unroll
        for (int p = 0; p < NPW-1; p++) accp[p] = accp[p+1];
        accp[NPW-1] = inc;

        // ---- self spikes from stashes (post-barrier => ordered) ----
        const float a0 = (r == 0) ? s_a : spkA[(par*CPC + lc)*32 + lane];
        const float b0 = (r == 0) ? s_b : spkB[(par*CPC + lc)*32 + lane];

        // ---- gather row tau+1 (published just above by producers) ----
        #pragma unroll
        for (int e = 1; e < EDGES; e++) svb[e-1] = ldg_relaxed(rowb + srcp[e] + lane);
        if (tau + 1 >= NB_INIT) {
            float mn = svb[0];
            #pragma unroll
            for (int e = 1; e < EDGES-1; e++) mn = fminf(mn, svb[e]);
            if (__any_sync(0xffffffffu, mn < -0.5f)) {
                #pragma unroll
                for (int e = 0; e < EDGES-1; e++) {
                    int guard = 0;
                    while (__any_sync(0xffffffffu, svb[e] == -1.0f)) {
                        svb[e] = ldg_relaxed(rowb + srcp[e+1] + lane);
                        if (++guard > (1 << 24)) break;
                    }
                }
            }
        }

        // ---- r0: publish s(tau+2) (post-shift slot0 + f=98 on s(tau) + f=99 on s(tau+1)),
        //      fix up slot1 with the f=98·s(tau+1) taps, stash for next body ----
        if (r == 0) {
            const int tn2 = tau + 2;
            if (tn2 < NB) {
                float hA = wh2p[0]*a0, hB = whp[0]*b0, hC = wh2p[0]*b0;
                #pragma unroll
                for (int e = 1; e < EDGES; e++) {
                    float va = sva[e-1], vb = svb[e-1];
                    hA = fmaf(wh2p[e], va, hA);
                    hB = fmaf(whp[e],  vb, hB);
                    hC = fmaf(wh2p[e], vb, hC);
                }
                float s_n;
                if (tn2 >= NB_INIT) {
                    float gv2 = lo2(accp[0]) + hA + hB + sapp * stvp[tn2 - NB_INIT] + bv;
                    s_n = __fdividef(1.0f, 1.0f + __expf(-gv2));
                    g_gens[(size_t)(tn2 - NB_INIT)*ROW + myoff] = gv2;
                    stg_relaxed(&g_spk[(size_t)tn2*ROW + myoff], s_n);
                } else {
                    s_n = g_spk[(size_t)tn2*ROW + myoff];
                }
                spkA[(((par^1))*CPC + lc)*32 + lane] = s_n;
                accp[0] = pk2(lo2(accp[0]), hi2(accp[0]) + hC);   // slot1 fixup
                s_a = s_n;
            }
        }

        // ---- fused scatter: acc[j] += w[j+1]·s(tau) + w[j]·s(tau+1);
        //      one weight stream serves both steps; inline prefetch row tau+2 ----
        const float* rowc = rowb + ROW;
        #pragma unroll
        for (int e = 0; e < EDGES; e++) {
            const float va = (e == 0) ? a0 : sva[e-1];
            const float vb = (e == 0) ? b0 : svb[e-1];
            const unsigned long long ssa = pk2(va, va);
            const unsigned long long ssb = pk2(vb, vb);
            if (e >= 1) sva[e-1] = ldg_relaxed(rowc + srcp[e] + lane);  // prefetch
            const float* wrow = wseg + e*RING2;
            const float4* wp = (const float4*)wrow;
            float4 F = wp[0];
            #pragma unroll
            for (int q = 0; q < 7; q++) {
                float4 Fn;
                if (q < 6) Fn = wp[q+1];
                else       Fn = make_float4(wrow[28], 0.f, 0.f, 0.f);
                fma2(accp[2*q],   pk2(F.x, F.y),  ssb);
                fma2(accp[2*q],   pk2(F.y, F.z),  ssa);
                fma2(accp[2*q+1], pk2(F.z, F.w),  ssb);
                fma2(accp[2*q+1], pk2(F.w, Fn.x), ssa);
                F = Fn;
            }
        }
    }
}

// ---------------- output assembly: transpose [t][c][b] -> [b][c][t] ----------------
__global__ void k_out(const float* __restrict__ init, float* __restrict__ out) {
    __shared__ float tile[128][33];
    int c = blockIdx.x, tid = threadIdx.x;
    float* out_s = out;                                      // (32,600,500)
    float* out_g = out + (size_t)BATCH*N_CELLS*NB;           // (32,600,400)

    for (int i = tid; i < BATCH*NB_INIT; i += 128) {
        int b = i / NB_INIT, t = i % NB_INIT;
        out_s[(size_t)b*(N_CELLS*NB) + (size_t)c*NB + t] =
            init[((size_t)b*N_CELLS + c)*NB_INIT + t];
    }
    for (int t0 = NB_INIT; t0 < NB; t0 += 128) {
        int chunk = min(128, NB - t0);
        __syncthreads();
        for (int i = tid; i < chunk*BATCH; i += 128) {
            int tl = i / BATCH, b = i % BATCH;
            tile[tl][b] = g_spk[(size_t)(t0+tl)*ROW + c*BATCH + b];
        }
        __syncthreads();
        for (int i = tid; i < chunk*BATCH; i += 128) {
            int b = i / chunk, tl = i % chunk;
            out_s[(size_t)b*(N_CELLS*NB) + (size_t)c*NB + (t0+tl)] = tile[tl][b];
        }
    }
    for (int t0 = 0; t0 < NSTEPS; t0 += 128) {
        int chunk = min(128, NSTEPS - t0);
        __syncthreads();
        for (int i = tid; i < chunk*BATCH; i += 128) {
            int tl = i / BATCH, b = i % BATCH;
            tile[tl][b] = g_gens[(size_t)(t0+tl)*ROW + c*BATCH + b];
        }
        __syncthreads();
        for (int i = tid; i < chunk*BATCH; i += 128) {
            int b = i / chunk, tl = i % chunk;
            out_g[(size_t)b*(N_CELLS*NSTEPS) + (size_t)c*NSTEPS + (t0+tl)] = tile[tl][b];
        }
    }
}

// ---------------- launch ----------------
extern "C" void kernel_launch(void* const* d_in, const int* in_sizes, int n_in,
                              void* d_out, int out_size) {
    const float* stim  = (const float*)d_in[0];   // (32,64,64)
    const float* init  = (const float*)d_in[1];   // (32,600,100)
    const float* spat  = (const float*)d_in[2];   // (600,64,64)
    const float* tcf   = (const float*)d_in[3];   // (600,100)
    const float* fbf   = (const float*)d_in[4];   // (600,100)
    const float* cpf   = (const float*)d_in[5];   // (600,20,100)
    const float* bias  = (const float*)d_in[6];   // (600,1)
    const int*   sel   = (const int*)d_in[7];     // (600,20)
    const float* stime = (const float*)d_in[8];   // (500,)
    float* out = (float*)d_out;

    cudaFuncSetAttribute(k_sim, cudaFuncAttributeMaxDynamicSharedMemorySize, SMEM_DYN);

    k_stimT<<<BATCH, 256>>>(stim);
    k_sapp<<<N_CELLS, 128>>>(spat);
    k_init<<<(NB*ROW + 255)/256, 256>>>(init);
    k_sim<<<NCTA, TPB, SMEM_DYN>>>(stime, tcf, fbf, cpf, bias, sel);
    k_out<<<N_CELLS, 128>>>(init, out);
}

// round 12
// speedup vs baseline: 1.1205x; 1.1205x over previous
#include <cuda_runtime.h>
#include <cuda_bf16.h>
#include <cstdint>

#define N_CELLS 600
#define HW      4096
#define NBF     100
#define MC      20
#define EDGES   21
#define NB      500
#define NB_INIT 100
#define BATCH   32
#define NSTEPS  400
#define ROW     (N_CELLS*BATCH)   /* 19200 */

// 5 cells per CTA, 5 warps per cell, 20 slots each: ring EXACTLY 100, zero pad gone
#define CPC     5
#define WPC     5
#define SLOTS   20
#define NPW     10                 /* f32x2 pairs per warp */
#define NQ      5                  /* float4 loads per edge per warp */
#define RING    100
#define TPB     (CPC*WPC*32)       /* 800 threads, 25 warps */
#define NCTA    (N_CELLS/CPC)      /* 120 CTAs -> 1 per SM, uniform */

// dynamic smem layout (bytes, 16-aligned blocks)
#define OFF_W    0                               /* float[CPC][EDGES][RING] = 42000 */
#define OFF_STV  42000                           /* float[CPC][NSTEPS]      =  8000 */
#define OFF_SRC  50000                           /* int  [CPC][EDGES] pad 448       */
#define OFF_WH   50448                           /* float[CPC][EDGES] pad 448       */
#define OFF_SPK  50896                           /* float[2][CPC][32]       =  1280 */
#define OFF_BND  52176                           /* float[2][CPC][WPC][32]  =  6400 */
#define SMEM_DYN 58576

// ---------------- scratch (no allocations allowed). +1 pad row for tail prefetch ----
__device__ float g_spk [(NB+1) * N_CELLS * BATCH];  // [t][c][b], canary -1 until written
__device__ float g_gens[NSTEPS * N_CELLS * BATCH];  // [t'][c][b]
__device__ float g_stimT[HW * BATCH];               // [hw][b]
__device__ float g_sapp [N_CELLS * BATCH];          // [c][b]

// ---------------- helpers ----------------
__device__ __forceinline__ float ldg_relaxed(const float* p) {
    float v;
    asm volatile("ld.relaxed.gpu.global.f32 %0, [%1];" : "=f"(v) : "l"(p));
    return v;
}
__device__ __forceinline__ void stg_relaxed(float* p, float v) {
    asm volatile("st.relaxed.gpu.global.f32 [%0], %1;" :: "l"(p), "f"(v) : "memory");
}
__device__ __forceinline__ unsigned long long pk2(float lo, float hi) {
    unsigned long long u;
    asm("mov.b64 %0, {%1, %2};" : "=l"(u) : "f"(lo), "f"(hi));
    return u;
}
__device__ __forceinline__ float lo2(unsigned long long u) {
    float a, b;
    asm("mov.b64 {%0, %1}, %2;" : "=f"(a), "=f"(b) : "l"(u));
    return a;
}
__device__ __forceinline__ float hi2(unsigned long long u) {
    float a, b;
    asm("mov.b64 {%0, %1}, %2;" : "=f"(a), "=f"(b) : "l"(u));
    return b;
}
__device__ __forceinline__ void fma2(unsigned long long& acc, unsigned long long w, unsigned long long s) {
    asm("fma.rn.f32x2 %0, %1, %2, %0;" : "+l"(acc) : "l"(w), "l"(s));
}
__device__ __forceinline__ void cellbar(int id) {
    asm volatile("bar.sync %0, %1;" :: "r"(id), "r"(WPC*32) : "memory");
}

// ---------------- setup: transpose stimulus to [hw][b] ----------------
__global__ void k_stimT(const float* __restrict__ stim) {
    int b = blockIdx.x;
    for (int i = threadIdx.x; i < HW; i += blockDim.x)
        g_stimT[i*BATCH + b] = stim[(size_t)b*HW + i];
}

// ---------------- setup: stim_applied[c][b] = stim_flat[b] . spat_flat[c] ----------------
__global__ void k_sapp(const float* __restrict__ spat) {
    __shared__ float red[128];
    int c = blockIdx.x, tid = threadIdx.x;
    int g = tid >> 5, b = tid & 31;
    float acc = 0.f;
    const float* sp = spat + (size_t)c*HW;
    #pragma unroll 8
    for (int m = 0; m < HW/4; m++) {
        int i = g + 4*m;
        acc += sp[i] * g_stimT[i*BATCH + b];
    }
    red[tid] = acc;
    __syncthreads();
    if (tid < 32)
        g_sapp[c*BATCH + tid] = red[tid] + red[tid+32] + red[tid+64] + red[tid+96];
}

// ---------------- setup: initial spikes transposed + canary fill ----------------
__global__ void k_init(const float* __restrict__ init) {
    int idx = blockIdx.x*blockDim.x + threadIdx.x;
    if (idx >= NB*ROW) return;
    int tau = idx / ROW, r = idx % ROW;
    int cc = r / BATCH, b = r % BATCH;
    g_spk[idx] = (tau < NB_INIT) ? init[((size_t)b*N_CELLS + cc)*NB_INIT + tau] : -1.0f;
}

// ---------------- simulation: 120 CTAs x 800 threads; 5 warps/cell, exact 100-ring ----
__global__ void __launch_bounds__(TPB, 1)
k_sim(const float* __restrict__ stime,      // (500)
      const float* __restrict__ tcf,        // (600,100)
      const float* __restrict__ fbf,        // (600,100)
      const float* __restrict__ cpf,        // (600,20,100)
      const float* __restrict__ bias,       // (600,1)
      const int*   __restrict__ sel)        // (600,20)
{
    extern __shared__ __align__(16) char dyn[];
    float* sw   = (float*)(dyn + OFF_W);     // [lc][e][j] tap-reversed; j==0 ZEROED (head extracted)
    float* sstv = (float*)(dyn + OFF_STV);   // [lc][t]
    int*   ssrc = (int*)  (dyn + OFF_SRC);   // [lc][e] = src*BATCH
    float* swh  = (float*)(dyn + OFF_WH);    // [lc][e] head tap weight w_rev[0] = filter[99]
    float* sspk = (float*)(dyn + OFF_SPK);   // [par][lc][32] self-spike stash
    float* sbnd = (float*)(dyn + OFF_BND);   // [par][lc][r][32] boundary export

    const int tid = threadIdx.x;
    const int c0 = blockIdx.x * CPC;

    // ---- prologue ----
    for (int i = tid; i < CPC*EDGES*RING; i += TPB) {
        int lc = i / (EDGES*RING), rr = i % (EDGES*RING);
        int e = rr / RING, j = rr % RING;
        int c = c0 + lc;
        float v = 0.0f;
        if (j >= 1)                            // j==0 is the head tap: lives in swh instead
            v = (e == 0) ? fbf[(size_t)c*NBF + (NBF-1-j)]
                         : cpf[((size_t)c*MC + (e-1))*NBF + (NBF-1-j)];
        sw[i] = v;
    }
    for (int i = tid; i < CPC*EDGES; i += TPB) {
        int lc = i / EDGES, e = i % EDGES;
        int c = c0 + lc;
        ssrc[i] = ((e == 0) ? c : sel[c*MC + (e-1)]) * BATCH;
        swh[i]  = (e == 0) ? fbf[(size_t)c*NBF + (NBF-1)]
                           : cpf[((size_t)c*MC + (e-1))*NBF + (NBF-1)];
    }
    for (int i = tid; i < CPC*NSTEPS; i += TPB) {
        int lc = i / NSTEPS, t = i % NSTEPS;
        int c = c0 + lc;
        float s = 0.f;
        #pragma unroll 4
        for (int f = 0; f < NBF; f++)
            s += __ldg(stime + t + f) * __ldg(tcf + (size_t)c*NBF + f);
        sstv[i] = s;
    }
    __syncthreads();

    const int wid = tid >> 5, lane = tid & 31;
    // SMSP-balanced map: publishers (r==0) = wids 0..4 -> SMSPs {0,1,2,3,0}
    const int lc = wid % CPC, r = wid / CPC;
    const int c = c0 + lc;
    const int barid = lc + 1;
    const int myoff = c*BATCH + lane;
    const float sapp = g_sapp[myoff];
    const float bv = bias[c];
    const float* wbase = sw + lc*(EDGES*RING) + r*SLOTS;   // 80r bytes: 16B-aligned
    const float* stvp  = sstv + lc*NSTEPS;
    const float* whp   = swh + lc*EDGES;
    const int*   srcp  = ssrc + lc*EDGES;                  // read inline (regs saved)

    // prologue stash: self spike for tau=0 (parity 0)
    if (r == 0) sspk[0*CPC*32 + lc*32 + lane] = g_spk[myoff];

    unsigned long long accp[NPW];
    #pragma unroll
    for (int p = 0; p < NPW; p++) accp[p] = 0ull;
    __syncthreads();

    // ---- prologue prefetch: gather row 0 (init-written, always valid) ----
    float sv[EDGES];
    #pragma unroll
    for (int e = 1; e < EDGES; e++) sv[e] = ldg_relaxed(g_spk + srcp[e] + lane);

    #pragma unroll 2
    for (int tau = 0; tau < NB; tau++) {
        const int par = tau & 1;
        const float* row = g_spk + (size_t)tau*ROW;

        // ---- validate prefetched gather (sv holds row tau, loaded last body) ----
        sv[0] = sspk[par*CPC*32 + lc*32 + lane];            // stashed last iter
        if (tau >= NB_INIT) {
            float mn = sv[1];
            #pragma unroll
            for (int e = 2; e < EDGES; e++) mn = fminf(mn, sv[e]);
            if (__any_sync(0xffffffffu, mn < -0.5f)) {
                #pragma unroll
                for (int e = 1; e < EDGES; e++) {
                    int guard = 0;
                    while (__any_sync(0xffffffffu, sv[e] == -1.0f)) {
                        sv[e] = ldg_relaxed(row + srcp[e] + lane);
                        if (++guard > (1 << 22)) break;   // degrade, never hang
                    }
                }
            }
        }

        // ---- PUBLISH-AHEAD: spike(tau+1) is complete right now; push it out early ----
        if (r == 0) {
            const int tn = tau + 1;
            if (tn < NB) {
                float s;
                if (tn >= NB_INIT) {
                    float h = hi2(accp[0]);               // slot1 pre-shift: taps f=1..98 done
                    #pragma unroll
                    for (int e = 0; e < EDGES; e++) h = fmaf(whp[e], sv[e], h);  // tap f=99
                    int t = tn - NB_INIT;
                    float gv = h + sapp * stvp[t] + bv;
                    s = __fdividef(1.0f, 1.0f + __expf(-gv));
                    g_gens[(size_t)t*ROW + myoff] = gv;
                    stg_relaxed(&g_spk[(size_t)tn*ROW + myoff], s);
                } else {
                    s = g_spk[(size_t)tn*ROW + myoff];    // prefetch init spike
                }
                sspk[(par^1)*CPC*32 + lc*32 + lane] = s;  // stash for next iter
            }
        } else {
            sbnd[par*CPC*WPC*32 + (lc*WPC + r)*32 + lane] = lo2(accp[0]);  // boundary export
        }
        cellbar(barid);

        // ---- shift segment down one slot; import neighbor's head (or 0 at tail) ----
        float incoming = (r < WPC-1)
            ? sbnd[par*CPC*WPC*32 + (lc*WPC + r + 1)*32 + lane] : 0.0f;
        #pragma unroll
        for (int p = 0; p < NPW-1; p++) accp[p] = pk2(hi2(accp[p]), lo2(accp[p+1]));
        accp[NPW-1] = pk2(hi2(accp[NPW-1]), incoming);

        // ---- bulk scatter with inline prefetch of row tau+1 (register-neutral) ----
        const float* nrow = row + ROW;
        #pragma unroll
        for (int e = 0; e < EDGES; e++) {
            unsigned long long ss = pk2(sv[e], sv[e]);
            if (e >= 1) sv[e] = ldg_relaxed(nrow + srcp[e] + lane);   // prefetch next row
            const float4* wp = (const float4*)(wbase + e*RING);
            #pragma unroll
            for (int q = 0; q < NQ; q++) {
                float4 w4 = wp[q];
                fma2(accp[2*q],   pk2(w4.x, w4.y), ss);
                fma2(accp[2*q+1], pk2(w4.z, w4.w), ss);
            }
        }
    }
}

// ---------------- output assembly: transpose [t][c][b] -> [b][c][t] ----------------
__global__ void k_out(const float* __restrict__ init, float* __restrict__ out) {
    __shared__ float tile[128][33];
    int c = blockIdx.x, tid = threadIdx.x;
    float* out_s = out;                                      // (32,600,500)
    float* out_g = out + (size_t)BATCH*N_CELLS*NB;           // (32,600,400)

    for (int i = tid; i < BATCH*NB_INIT; i += 128) {
        int b = i / NB_INIT, t = i % NB_INIT;
        out_s[(size_t)b*(N_CELLS*NB) + (size_t)c*NB + t] =
            init[((size_t)b*N_CELLS + c)*NB_INIT + t];
    }
    for (int t0 = NB_INIT; t0 < NB; t0 += 128) {
        int chunk = min(128, NB - t0);
        __syncthreads();
        for (int i = tid; i < chunk*BATCH; i += 128) {
            int tl = i / BATCH, b = i % BATCH;
            tile[tl][b] = g_spk[(size_t)(t0+tl)*ROW + c*BATCH + b];
        }
        __syncthreads();
        for (int i = tid; i < chunk*BATCH; i += 128) {
            int b = i / chunk, tl = i % chunk;
            out_s[(size_t)b*(N_CELLS*NB) + (size_t)c*NB + (t0+tl)] = tile[tl][b];
        }
    }
    for (int t0 = 0; t0 < NSTEPS; t0 += 128) {
        int chunk = min(128, NSTEPS - t0);
        __syncthreads();
        for (int i = tid; i < chunk*BATCH; i += 128) {
            int tl = i / BATCH, b = i % BATCH;
            tile[tl][b] = g_gens[(size_t)(t0+tl)*ROW + c*BATCH + b];
        }
        __syncthreads();
        for (int i = tid; i < chunk*BATCH; i += 128) {
            int b = i / chunk, tl = i % chunk;
            out_g[(size_t)b*(N_CELLS*NSTEPS) + (size_t)c*NSTEPS + (t0+tl)] = tile[tl][b];
        }
    }
}

// ---------------- launch ----------------
extern "C" void kernel_launch(void* const* d_in, const int* in_sizes, int n_in,
                              void* d_out, int out_size) {
    const float* stim  = (const float*)d_in[0];   // (32,64,64)
    const float* init  = (const float*)d_in[1];   // (32,600,100)
    const float* spat  = (const float*)d_in[2];   // (600,64,64)
    const float* tcf   = (const float*)d_in[3];   // (600,100)
    const float* fbf   = (const float*)d_in[4];   // (600,100)
    const float* cpf   = (const float*)d_in[5];   // (600,20,100)
    const float* bias  = (const float*)d_in[6];   // (600,1)
    const int*   sel   = (const int*)d_in[7];     // (600,20)
    const float* stime = (const float*)d_in[8];   // (500,)
    float* out = (float*)d_out;

    cudaFuncSetAttribute(k_sim, cudaFuncAttributeMaxDynamicSharedMemorySize, SMEM_DYN);

    k_stimT<<<BATCH, 256>>>(stim);
    k_sapp<<<N_CELLS, 128>>>(spat);
    k_init<<<(NB*ROW + 255)/256, 256>>>(init);
    k_sim<<<NCTA, TPB, SMEM_DYN>>>(stime, tcf, fbf, cpf, bias, sel);
    k_out<<<N_CELLS, 128>>>(init, out);
}

// round 13
// speedup vs baseline: 1.1499x; 1.0262x over previous
#include <cuda_runtime.h>
#include <cuda_bf16.h>
#include <cstdint>

#define N_CELLS 600
#define HW      4096
#define NBF     100
#define MC      20
#define EDGES   21
#define NB      500
#define NB_INIT 100
#define BATCH   32
#define NSTEPS  400
#define ROW     (N_CELLS*BATCH)   /* 19200 */

// 5 cells per CTA, 4 warps per cell (systolic ring, 28 slots each, 112-slot padded ring)
#define CPC     5
#define WPC     4
#define SLOTS   28
#define NPW     14                 /* f32x2 pairs per warp */
#define NQ      7                  /* float4 loads per edge per warp */
#define RING    112
#define TPB     (CPC*WPC*32)       /* 640 threads */
#define NCTA    (N_CELLS/CPC)      /* 120 CTAs -> 1 per SM, uniform load */

// dynamic smem layout (bytes)
#define OFF_W    0                               /* float[CPC][EDGES][RING] = 47040 */
#define OFF_STV  47040                           /* float[CPC][NSTEPS]      =  8000 */
#define OFF_SRC  55040                           /* int  [CPC][EDGES]  (pad 448)    */
#define OFF_WH   55488                           /* float[CPC][EDGES]  (pad 448)    */
#define OFF_SPK  55936                           /* float[2][CPC][32]       =  1280 */
#define OFF_BND  57216                           /* float[2][CPC][WPC][32]  =  5120 */
#define SMEM_DYN 62336

// ---------------- scratch: __device__ globals (no allocations allowed) ----------------
// +1 pad row: the inline prefetch at tau=NB-1 reads row NB (never used, never canary-polled)
__device__ float g_spk [(NB+1) * N_CELLS * BATCH];  // [t][c][b], canary -1 until written
__device__ float g_gens[NSTEPS * N_CELLS * BATCH];  // [t'][c][b]
__device__ float g_stimT[HW * BATCH];               // [hw][b]
__device__ float g_sapp [N_CELLS * BATCH];          // [c][b]

// ---------------- helpers ----------------
__device__ __forceinline__ float ldg_relaxed(const float* p) {
    float v;
    asm volatile("ld.relaxed.gpu.global.f32 %0, [%1];" : "=f"(v) : "l"(p));
    return v;
}
__device__ __forceinline__ void stg_relaxed(float* p, float v) {
    asm volatile("st.relaxed.gpu.global.f32 [%0], %1;" :: "l"(p), "f"(v) : "memory");
}
__device__ __forceinline__ unsigned long long pk2(float lo, float hi) {
    unsigned long long u;
    asm("mov.b64 %0, {%1, %2};" : "=l"(u) : "f"(lo), "f"(hi));
    return u;
}
__device__ __forceinline__ float lo2(unsigned long long u) {
    float a, b;
    asm("mov.b64 {%0, %1}, %2;" : "=f"(a), "=f"(b) : "l"(u));
    return a;
}
__device__ __forceinline__ float hi2(unsigned long long u) {
    float a, b;
    asm("mov.b64 {%0, %1}, %2;" : "=f"(a), "=f"(b) : "l"(u));
    return b;
}
__device__ __forceinline__ void fma2(unsigned long long& acc, unsigned long long w, unsigned long long s) {
    asm("fma.rn.f32x2 %0, %1, %2, %0;" : "+l"(acc) : "l"(w), "l"(s));
}
__device__ __forceinline__ void cellbar(int id) {
    asm volatile("bar.sync %0, %1;" :: "r"(id), "r"(WPC*32) : "memory");
}

// ---------------- setup: transpose stimulus to [hw][b] ----------------
__global__ void k_stimT(const float* __restrict__ stim) {
    int b = blockIdx.x;
    for (int i = threadIdx.x; i < HW; i += blockDim.x)
        g_stimT[i*BATCH + b] = stim[(size_t)b*HW + i];
}

// ---------------- setup: stim_applied[c][b] = stim_flat[b] . spat_flat[c] ----------------
__global__ void k_sapp(const float* __restrict__ spat) {
    __shared__ float red[128];
    int c = blockIdx.x;
    int tid = threadIdx.x;
    int g = tid >> 5, b = tid & 31;
    float acc = 0.f;
    const float* sp = spat + (size_t)c*HW;
    #pragma unroll 8
    for (int m = 0; m < HW/4; m++) {
        int i = g + 4*m;
        acc += sp[i] * g_stimT[i*BATCH + b];
    }
    red[tid] = acc;
    __syncthreads();
    if (tid < 32)
        g_sapp[c*BATCH + tid] = red[tid] + red[tid+32] + red[tid+64] + red[tid+96];
}

// ---------------- setup: initial spikes transposed + canary fill ----------------
__global__ void k_init(const float* __restrict__ init) {
    int idx = blockIdx.x*blockDim.x + threadIdx.x;
    if (idx >= NB*ROW) return;
    int tau = idx / ROW, r = idx % ROW;
    int cc = r / BATCH, b = r % BATCH;
    g_spk[idx] = (tau < NB_INIT) ? init[((size_t)b*N_CELLS + cc)*NB_INIT + tau] : -1.0f;
}

// ---------------- simulation: SMSP-balanced publish-ahead systolic ring ----------
__global__ void __launch_bounds__(TPB, 1)
k_sim(const float* __restrict__ stime,      // (500)
      const float* __restrict__ tcf,        // (600,100)
      const float* __restrict__ fbf,        // (600,100)
      const float* __restrict__ cpf,        // (600,20,100)
      const float* __restrict__ bias,       // (600,1)
      const int*   __restrict__ sel)        // (600,20)
{
    extern __shared__ __align__(16) char dyn[];
    float* sw   = (float*)(dyn + OFF_W);     // [lc][e][j] tap-reversed; j==0 ZEROED (head extracted)
    float* sstv = (float*)(dyn + OFF_STV);   // [lc][t]
    int*   ssrc = (int*)  (dyn + OFF_SRC);   // [lc][e] = src*BATCH
    float* swh  = (float*)(dyn + OFF_WH);    // [lc][e] head tap weight w_rev[0] = filter[99]
    float* sspk = (float*)(dyn + OFF_SPK);   // [par][lc][32] self-spike stash
    float* sbnd = (float*)(dyn + OFF_BND);   // [par][lc][r][32] boundary export

    const int tid = threadIdx.x;
    const int c0 = blockIdx.x * CPC;

    // ---- prologue ----
    for (int i = tid; i < CPC*EDGES*RING; i += TPB) {
        int lc = i / (EDGES*RING), rr = i % (EDGES*RING);
        int e = rr / RING, j = rr % RING;
        int c = c0 + lc;
        float v = 0.0f;
        if (j >= 1 && j < NBF)                 // j==0 is the head tap: lives in swh instead
            v = (e == 0) ? fbf[(size_t)c*NBF + (NBF-1-j)]
                         : cpf[((size_t)c*MC + (e-1))*NBF + (NBF-1-j)];
        sw[i] = v;
    }
    for (int i = tid; i < CPC*EDGES; i += TPB) {
        int lc = i / EDGES, e = i % EDGES;
        int c = c0 + lc;
        ssrc[i] = ((e == 0) ? c : sel[c*MC + (e-1)]) * BATCH;
        swh[i]  = (e == 0) ? fbf[(size_t)c*NBF + (NBF-1)]
                           : cpf[((size_t)c*MC + (e-1))*NBF + (NBF-1)];
    }
    for (int i = tid; i < CPC*NSTEPS; i += TPB) {
        int lc = i / NSTEPS, t = i % NSTEPS;
        int c = c0 + lc;
        float s = 0.f;
        #pragma unroll 4
        for (int f = 0; f < NBF; f++)
            s += __ldg(stime + t + f) * __ldg(tcf + (size_t)c*NBF + f);
        sstv[i] = s;
    }
    __syncthreads();

    const int wid = tid >> 5, lane = tid & 31;
    // SMSP-balanced map: publishers (r==0) spread across schedulers
    const int lc = wid % CPC, r = wid / CPC;
    const int c = c0 + lc;
    const int barid = lc + 1;
    const int myoff = c*BATCH + lane;
    const float sapp = g_sapp[myoff];
    const float bv = bias[c];
    const float* wbase = sw + lc*(EDGES*RING) + r*SLOTS;
    const float* stvp  = sstv + lc*NSTEPS;
    const float* whp   = swh + lc*EDGES;

    int off[EDGES-1];
    #pragma unroll
    for (int e = 0; e < EDGES-1; e++) off[e] = ssrc[lc*EDGES + e + 1] + lane;

    // prologue stash: self spike for tau=0 (parity 0)
    if (r == 0) sspk[0*CPC*32 + lc*32 + lane] = g_spk[myoff];

    unsigned long long accp[NPW];
    #pragma unroll
    for (int p = 0; p < NPW; p++) accp[p] = 0ull;
    __syncthreads();

    // ---- prologue prefetch: gather row 0 (init-written, always valid) ----
    float sv[EDGES];
    #pragma unroll
    for (int e = 1; e < EDGES; e++) sv[e] = ldg_relaxed(g_spk + off[e-1]);

    #pragma unroll 2
    for (int tau = 0; tau < NB; tau++) {
        const int par = tau & 1;
        const float* row = g_spk + (size_t)tau*ROW;

        // ---- validate prefetched gather (sv holds row tau, loaded last body).
        //      BATCHED re-poll: each sweep reloads ALL still-canary edges in
        //      parallel (MLP ~20) and votes ONCE -> one L2 latency per sweep,
        //      not one per straggling edge. ----
        sv[0] = sspk[par*CPC*32 + lc*32 + lane];            // stashed last iter
        if (tau >= NB_INIT) {
            float mn = sv[1];
            #pragma unroll
            for (int e = 2; e < EDGES; e++) mn = fminf(mn, sv[e]);
            int guard = 0;
            while (__any_sync(0xffffffffu, mn < -0.5f)) {
                mn = 1.0f;
                #pragma unroll
                for (int e = 1; e < EDGES; e++) {
                    if (sv[e] == -1.0f) sv[e] = ldg_relaxed(row + off[e-1]);
                    mn = fminf(mn, sv[e]);
                }
                if (++guard > (1 << 20)) break;   // degrade, never hang
            }
        }

        // ---- PUBLISH-AHEAD: spike(tau+1) is complete right now; push it out early ----
        if (r == 0) {
            const int tn = tau + 1;
            if (tn < NB) {
                float s;
                if (tn >= NB_INIT) {
                    float h = hi2(accp[0]);               // slot1 pre-shift: taps f=1..98 done
                    #pragma unroll
                    for (int e = 0; e < EDGES; e++) h = fmaf(whp[e], sv[e], h);  // tap f=99
                    int t = tn - NB_INIT;
                    float gv = h + sapp * stvp[t] + bv;
                    s = __fdividef(1.0f, 1.0f + __expf(-gv));
                    g_gens[(size_t)t*ROW + myoff] = gv;
                    stg_relaxed(&g_spk[(size_t)tn*ROW + myoff], s);
                } else {
                    s = g_spk[(size_t)tn*ROW + myoff];    // prefetch init spike
                }
                sspk[(par^1)*CPC*32 + lc*32 + lane] = s;  // stash for next iter
            }
        } else {
            sbnd[par*CPC*WPC*32 + (lc*WPC + r)*32 + lane] = lo2(accp[0]);  // boundary export
        }
        cellbar(barid);

        // ---- shift segment down one slot; import neighbor's head (or 0 at tail) ----
        float incoming = (r < WPC-1)
            ? sbnd[par*CPC*WPC*32 + (lc*WPC + r + 1)*32 + lane] : 0.0f;
        #pragma unroll
        for (int p = 0; p < NPW-1; p++) accp[p] = pk2(hi2(accp[p]), lo2(accp[p+1]));
        accp[NPW-1] = pk2(hi2(accp[NPW-1]), incoming);

        // ---- bulk scatter with inline prefetch of row tau+1 (register-neutral) ----
        const float* nrow = row + ROW;
        #pragma unroll
        for (int e = 0; e < EDGES; e++) {
            unsigned long long ss = pk2(sv[e], sv[e]);
            if (e >= 1) sv[e] = ldg_relaxed(nrow + off[e-1]);   // prefetch next row
            const float4* wp = (const float4*)(wbase + e*RING);
            #pragma unroll
            for (int q = 0; q < NQ; q++) {
                float4 w4 = wp[q];
                fma2(accp[2*q],   pk2(w4.x, w4.y), ss);
                fma2(accp[2*q+1], pk2(w4.z, w4.w), ss);
            }
        }
    }
}

// ---------------- output assembly: transpose [t][c][b] -> [b][c][t] ----------------
__global__ void k_out(const float* __restrict__ init, float* __restrict__ out) {
    __shared__ float tile[128][33];
    int c = blockIdx.x, tid = threadIdx.x;
    float* out_s = out;                                      // (32,600,500)
    float* out_g = out + (size_t)BATCH*N_CELLS*NB;           // (32,600,400)

    for (int i = tid; i < BATCH*NB_INIT; i += 128) {
        int b = i / NB_INIT, t = i % NB_INIT;
        out_s[(size_t)b*(N_CELLS*NB) + (size_t)c*NB + t] =
            init[((size_t)b*N_CELLS + c)*NB_INIT + t];
    }
    for (int t0 = NB_INIT; t0 < NB; t0 += 128) {
        int chunk = min(128, NB - t0);
        __syncthreads();
        for (int i = tid; i < chunk*BATCH; i += 128) {
            int tl = i / BATCH, b = i % BATCH;
            tile[tl][b] = g_spk[(size_t)(t0+tl)*ROW + c*BATCH + b];
        }
        __syncthreads();
        for (int i = tid; i < chunk*BATCH; i += 128) {
            int b = i / chunk, tl = i % chunk;
            out_s[(size_t)b*(N_CELLS*NB) + (size_t)c*NB + (t0+tl)] = tile[tl][b];
        }
    }
    for (int t0 = 0; t0 < NSTEPS; t0 += 128) {
        int chunk = min(128, NSTEPS - t0);
        __syncthreads();
        for (int i = tid; i < chunk*BATCH; i += 128) {
            int tl = i / BATCH, b = i % BATCH;
            tile[tl][b] = g_gens[(size_t)(t0+tl)*ROW + c*BATCH + b];
        }
        __syncthreads();
        for (int i = tid; i < chunk*BATCH; i += 128) {
            int b = i / chunk, tl = i % chunk;
            out_g[(size_t)b*(N_CELLS*NSTEPS) + (size_t)c*NSTEPS + (t0+tl)] = tile[tl][b];
        }
    }
}

// ---------------- launch ----------------
extern "C" void kernel_launch(void* const* d_in, const int* in_sizes, int n_in,
                              void* d_out, int out_size) {
    const float* stim  = (const float*)d_in[0];   // (32,64,64)
    const float* init  = (const float*)d_in[1];   // (32,600,100)
    const float* spat  = (const float*)d_in[2];   // (600,64,64)
    const float* tcf   = (const float*)d_in[3];   // (600,100)
    const float* fbf   = (const float*)d_in[4];   // (600,100)
    const float* cpf   = (const float*)d_in[5];   // (600,20,100)
    const float* bias  = (const float*)d_in[6];   // (600,1)
    const int*   sel   = (const int*)d_in[7];     // (600,20)
    const float* stime = (const float*)d_in[8];   // (500,)
    float* out = (float*)d_out;

    cudaFuncSetAttribute(k_sim, cudaFuncAttributeMaxDynamicSharedMemorySize, SMEM_DYN);

    k_stimT<<<BATCH, 256>>>(stim);
    k_sapp<<<N_CELLS, 128>>>(spat);
    k_init<<<(NB*ROW + 255)/256, 256>>>(init);
    k_sim<<<NCTA, TPB, SMEM_DYN>>>(stime, tcf, fbf, cpf, bias, sel);
    k_out<<<N_CELLS, 128>>>(init, out);
}